// round 11
// baseline (speedup 1.0000x reference)
#include <cuda_runtime.h>
#include <math_constants.h>

// MAM dense: C[n,j] = max_k(x[n,k]*w[j,k]) + min_k(x[n,k]*w[j,k]) + bias[j]
// x: [2048, 512] f32, w: [256, 512] f32, bias: [256] f32, out: [2048, 256] f32
//
// R11: cut l1tex DELIVERED BYTES (R9's null result proved cost = per-lane
// bytes, not LDS instruction count). Thread tile 2n x 2j -> 4n x 2j:
// 3 B/product instead of 4. Tile 32n x 32j, 128 threads, grid 512 CTAs
// (4v3 residency, +15.6% imbalance accepted against a 25% lower floor).
// Inner k: 1 LDS.128 (a, conflict-free) + 1 LDS.64 (b, broadcast) ->
// 8 FMUL + 8 FMAX + 8 FMIN into 16 accumulators.

constexpr int IN_F  = 512;
constexpr int OUT_F = 256;
constexpr int NROWS = 2048;

constexpr int TN = 32;
constexpr int TJ = 32;
constexpr int KB = 32;
constexpr int NCH = IN_F / KB;                   // 16
constexpr int TILES_J = OUT_F / TJ;              // 8
constexpr int NTILES  = (NROWS / TN) * TILES_J;  // 512
constexpr int THREADS = 128;

constexpr int XLD = 36;  // xs[k][n] stride: mult of 4 -> LDS.128 aligned
constexpr int WLD = 34;  // ws[k][j] stride: even -> LDS.64 aligned

__global__ __launch_bounds__(THREADS, 4)
void mam_kernel(const float* __restrict__ x,
                const float* __restrict__ w,
                const float* __restrict__ bias,
                float* __restrict__ out)
{
    __shared__ __align__(16) float xs[KB][XLD];   // k-major x tile (32n)
    __shared__ __align__(16) float ws[KB][WLD];   // k-major w tile (32j)

    const int tid = threadIdx.x;
    const int tn  = tid & 7;           // 0..7  -> n group of 4
    const int tj  = tid >> 3;          // 0..15 -> j pair
    const int j0  = (blockIdx.x & (TILES_J - 1)) * TJ;
    const int n0  = (blockIdx.x / TILES_J) * TN;

    // Loader mapping (coalesced: 4 consecutive rows per warp quarter).
    const int lr  = tid >> 3;          // 0..15 (rows lr and lr+16)
    const int lkq = (tid & 7) * 4;     // k quad: 0,4,...,28

    const float* xb = &x[(n0 + lr) * IN_F + lkq];
    const float* wb = &w[(j0 + lr) * IN_F + lkq];

    float mx[4][2], mn[4][2];
#pragma unroll
    for (int i = 0; i < 4; i++)
#pragma unroll
        for (int jj = 0; jj < 2; jj++) {
            mx[i][jj] = -CUDART_INF_F;
            mn[i][jj] =  CUDART_INF_F;
        }

    // Prefetch chunk 0 (x: rows lr, lr+16; w: rows lr, lr+16).
    float4 xv0 = *reinterpret_cast<const float4*>(xb);
    float4 xv1 = *reinterpret_cast<const float4*>(xb + 16 * IN_F);
    float4 wv0 = *reinterpret_cast<const float4*>(wb);
    float4 wv1 = *reinterpret_cast<const float4*>(wb + 16 * IN_F);

    const float* agp = &xs[0][4 * tn];
    const float* bgp = &ws[0][2 * tj];

    for (int c = 0; c < NCH; c++) {
        // STS prefetched chunk (k-major scatter).
        xs[lkq + 0][lr]      = xv0.x; xs[lkq + 1][lr]      = xv0.y;
        xs[lkq + 2][lr]      = xv0.z; xs[lkq + 3][lr]      = xv0.w;
        xs[lkq + 0][lr + 16] = xv1.x; xs[lkq + 1][lr + 16] = xv1.y;
        xs[lkq + 2][lr + 16] = xv1.z; xs[lkq + 3][lr + 16] = xv1.w;
        ws[lkq + 0][lr]      = wv0.x; ws[lkq + 1][lr]      = wv0.y;
        ws[lkq + 2][lr]      = wv0.z; ws[lkq + 3][lr]      = wv0.w;
        ws[lkq + 0][lr + 16] = wv1.x; ws[lkq + 1][lr + 16] = wv1.y;
        ws[lkq + 2][lr + 16] = wv1.z; ws[lkq + 3][lr + 16] = wv1.w;
        __syncthreads();

        // Prefetch next chunk while computing this one.
        if (c + 1 < NCH) {
            const int kn = (c + 1) * KB;
            xv0 = *reinterpret_cast<const float4*>(xb + kn);
            xv1 = *reinterpret_cast<const float4*>(xb + 16 * IN_F + kn);
            wv0 = *reinterpret_cast<const float4*>(wb + kn);
            wv1 = *reinterpret_cast<const float4*>(wb + 16 * IN_F + kn);
        }

#pragma unroll
        for (int k = 0; k < KB; k++) {
            const float4 a = *reinterpret_cast<const float4*>(agp + k * XLD);
            const float2 b = *reinterpret_cast<const float2*>(bgp + k * WLD);
            float p;
            p = a.x * b.x; mx[0][0] = fmaxf(mx[0][0], p); mn[0][0] = fminf(mn[0][0], p);
            p = a.x * b.y; mx[0][1] = fmaxf(mx[0][1], p); mn[0][1] = fminf(mn[0][1], p);
            p = a.y * b.x; mx[1][0] = fmaxf(mx[1][0], p); mn[1][0] = fminf(mn[1][0], p);
            p = a.y * b.y; mx[1][1] = fmaxf(mx[1][1], p); mn[1][1] = fminf(mn[1][1], p);
            p = a.z * b.x; mx[2][0] = fmaxf(mx[2][0], p); mn[2][0] = fminf(mn[2][0], p);
            p = a.z * b.y; mx[2][1] = fmaxf(mx[2][1], p); mn[2][1] = fminf(mn[2][1], p);
            p = a.w * b.x; mx[3][0] = fmaxf(mx[3][0], p); mn[3][0] = fminf(mn[3][0], p);
            p = a.w * b.y; mx[3][1] = fmaxf(mx[3][1], p); mn[3][1] = fminf(mn[3][1], p);
        }
        __syncthreads();
    }

    // Epilogue: C = max + min + bias (four STG.64 per thread).
    const int j = j0 + 2 * tj;
    const int n = n0 + 4 * tn;
    const float b0 = bias[j];
    const float b1 = bias[j + 1];
#pragma unroll
    for (int i = 0; i < 4; i++) {
        float2 r;
        r.x = mx[i][0] + mn[i][0] + b0;
        r.y = mx[i][1] + mn[i][1] + b1;
        *reinterpret_cast<float2*>(&out[(n + i) * OUT_F + j]) = r;
    }
}

extern "C" void kernel_launch(void* const* d_in, const int* in_sizes, int n_in,
                              void* d_out, int out_size)
{
    const float* x    = (const float*)d_in[0];   // [2048, 512]
    const float* w    = (const float*)d_in[1];   // [256, 512]
    const float* bias = (const float*)d_in[2];   // [256]
    float* out        = (float*)d_out;           // [2048, 256]

    mam_kernel<<<NTILES, THREADS>>>(x, w, bias, out);
}

// round 13
// speedup vs baseline: 1.2817x; 1.2817x over previous
#include <cuda_runtime.h>
#include <math_constants.h>

// MAM dense: C[n,j] = max_k(x[n,k]*w[j,k]) + min_k(x[n,k]*w[j,k]) + bias[j]
// x: [2048, 512] f32, w: [256, 512] f32, bias: [256] f32, out: [2048, 256] f32
//
// R12: R9 (best tied, 37.6us) + double-buffered smem -> ONE __syncthreads per
// k-chunk (16 barriers vs 32). Model (calibrated R7-R11): issue floor 3 ops/
// product = 42.5K cyc/SMSP is tiling-invariant; issue efficiency needs ~7
// warps/SMSP -> 2n x 2j tile, 1024 CTAs (7v6), 128 thr is the right shape.
// Remaining slack over floor = barrier/staging overhead; this round cuts it.

constexpr int IN_F  = 512;
constexpr int OUT_F = 256;
constexpr int NROWS = 2048;

constexpr int TN = 32;
constexpr int TJ = 16;
constexpr int KB = 32;
constexpr int NCH = IN_F / KB;                   // 16
constexpr int TILES_J = OUT_F / TJ;              // 16
constexpr int NTILES  = (NROWS / TN) * TILES_J;  // 1024
constexpr int THREADS = 128;

constexpr int XLD2 = 68;   // floats per k2-row of xs2 (17*16B)
constexpr int WLD2 = 36;   // floats per k2-row of ws2 (9*16B)

__global__ __launch_bounds__(THREADS, 7)
void mam_kernel(const float* __restrict__ x,
                const float* __restrict__ w,
                const float* __restrict__ bias,
                float* __restrict__ out)
{
    // Double-buffered k-pair-packed tiles.
    __shared__ __align__(16) float xs2[2][(KB / 2) * XLD2];
    __shared__ __align__(16) float ws2[2][(KB / 2) * WLD2];

    const int tid = threadIdx.x;
    const int tn4 = tid >> 3;          // 0..15 -> n pair
    const int tj3 = tid & 7;           // 0..7  -> j pair
    const int j0  = (blockIdx.x & (TILES_J - 1)) * TJ;
    const int n0  = (blockIdx.x / TILES_J) * TN;

    // Loader mapping (coalesced: 4 consecutive rows per warp quarter).
    const int lr  = tid >> 3;          // 0..15
    const int lkq = (tid & 7) * 4;     // 0,4,...,28
    const int lk2 = lkq >> 1;          // k2 base

    const float* xb = &x[(n0 + lr) * IN_F + lkq];   // rows lr, lr+16
    const float* wb = &w[(j0 + lr) * IN_F + lkq];   // row lr

    float mx[2][2], mn[2][2];
#pragma unroll
    for (int i = 0; i < 2; i++)
#pragma unroll
        for (int jj = 0; jj < 2; jj++) {
            mx[i][jj] = -CUDART_INF_F;
            mn[i][jj] =  CUDART_INF_F;
        }

    // Prefetch chunk 0 and stage into buffer 0.
    float4 xv0 = *reinterpret_cast<const float4*>(xb);
    float4 xv1 = *reinterpret_cast<const float4*>(xb + 16 * IN_F);
    float4 wv  = *reinterpret_cast<const float4*>(wb);
    {
        float* xa = xs2[0] + lk2 * XLD2 + 2 * lr;
        *reinterpret_cast<float2*>(xa)        = make_float2(xv0.x, xv0.y);
        *reinterpret_cast<float2*>(xa + XLD2) = make_float2(xv0.z, xv0.w);
        float* xc = xs2[0] + lk2 * XLD2 + 2 * (lr + 16);
        *reinterpret_cast<float2*>(xc)        = make_float2(xv1.x, xv1.y);
        *reinterpret_cast<float2*>(xc + XLD2) = make_float2(xv1.z, xv1.w);
        float* wa = ws2[0] + lk2 * WLD2 + 2 * lr;
        *reinterpret_cast<float2*>(wa)        = make_float2(wv.x, wv.y);
        *reinterpret_cast<float2*>(wa + WLD2) = make_float2(wv.z, wv.w);
    }
    __syncthreads();   // buffer 0 ready

    for (int c = 0; c < NCH; c++) {
        // LDG next chunk (before computing current -> latency overlapped).
        const bool more = (c + 1) < NCH;
        if (more) {
            const int kn = (c + 1) * KB;
            xv0 = *reinterpret_cast<const float4*>(xb + kn);
            xv1 = *reinterpret_cast<const float4*>(xb + 16 * IN_F + kn);
            wv  = *reinterpret_cast<const float4*>(wb + kn);
        }

        // Compute current buffer.
        const float* agp = xs2[c & 1] + 4 * tn4;
        const float* bgp = ws2[c & 1] + 4 * tj3;
#pragma unroll
        for (int k2 = 0; k2 < KB / 2; k2++) {
            // a = {x[k0,n0], x[k1,n0], x[k0,n1], x[k1,n1]}
            // b = {w[k0,j0], w[k1,j0], w[k0,j1], w[k1,j1]}
            const float4 a = *reinterpret_cast<const float4*>(agp + k2 * XLD2);
            const float4 b = *reinterpret_cast<const float4*>(bgp + k2 * WLD2);

            const float p000 = a.x * b.x;
            const float p001 = a.y * b.y;
            const float p010 = a.x * b.z;
            const float p011 = a.y * b.w;
            const float p100 = a.z * b.x;
            const float p101 = a.w * b.y;
            const float p110 = a.z * b.z;
            const float p111 = a.w * b.w;

            mx[0][0] = fmaxf(mx[0][0], fmaxf(p000, p001));
            mn[0][0] = fminf(mn[0][0], fminf(p000, p001));
            mx[0][1] = fmaxf(mx[0][1], fmaxf(p010, p011));
            mn[0][1] = fminf(mn[0][1], fminf(p010, p011));
            mx[1][0] = fmaxf(mx[1][0], fmaxf(p100, p101));
            mn[1][0] = fminf(mn[1][0], fminf(p100, p101));
            mx[1][1] = fmaxf(mx[1][1], fmaxf(p110, p111));
            mn[1][1] = fminf(mn[1][1], fminf(p110, p111));
        }

        // Stage next chunk into the OTHER buffer, then one barrier.
        // The barrier at end of iter c guarantees:
        //  (a) everyone finished computing buf[c&1] before iter c+1 stores
        //      into it (stores at iter c+1 target buf[c&1]... wait, iter c+1
        //      stores buf[(c+2)&1] = buf[c&1] -- and all warps passed this
        //      barrier AFTER computing buf[c&1]);
        //  (b) the STS of buf[(c+1)&1] below is visible to all warps before
        //      iter c+1 reads it.
        if (more) {
            const int nb = (c + 1) & 1;
            float* xa = xs2[nb] + lk2 * XLD2 + 2 * lr;
            *reinterpret_cast<float2*>(xa)        = make_float2(xv0.x, xv0.y);
            *reinterpret_cast<float2*>(xa + XLD2) = make_float2(xv0.z, xv0.w);
            float* xc = xs2[nb] + lk2 * XLD2 + 2 * (lr + 16);
            *reinterpret_cast<float2*>(xc)        = make_float2(xv1.x, xv1.y);
            *reinterpret_cast<float2*>(xc + XLD2) = make_float2(xv1.z, xv1.w);
            float* wa = ws2[nb] + lk2 * WLD2 + 2 * lr;
            *reinterpret_cast<float2*>(wa)        = make_float2(wv.x, wv.y);
            *reinterpret_cast<float2*>(wa + WLD2) = make_float2(wv.z, wv.w);
            __syncthreads();
        }
    }

    // Epilogue: C = max + min + bias (two STG.64).
    const int j = j0 + 2 * tj3;
    const int n = n0 + 2 * tn4;
    const float b0 = bias[j];
    const float b1 = bias[j + 1];
#pragma unroll
    for (int i = 0; i < 2; i++) {
        float2 r;
        r.x = mx[i][0] + mn[i][0] + b0;
        r.y = mx[i][1] + mn[i][1] + b1;
        *reinterpret_cast<float2*>(&out[(n + i) * OUT_F + j]) = r;
    }
}

extern "C" void kernel_launch(void* const* d_in, const int* in_sizes, int n_in,
                              void* d_out, int out_size)
{
    const float* x    = (const float*)d_in[0];   // [2048, 512]
    const float* w    = (const float*)d_in[1];   // [256, 512]
    const float* bias = (const float*)d_in[2];   // [256]
    float* out        = (float*)d_out;           // [2048, 256]

    mam_kernel<<<NTILES, THREADS>>>(x, w, bias, out);
}